// round 9
// baseline (speedup 1.0000x reference)
#include <cuda_runtime.h>
#include <cuda_fp16.h>
#include <cstdint>

// ---------------- problem constants ----------------
#define B_     4
#define S_     16
#define NF     64            // frames = B*S
#define H_     32
#define W_     32
#define HW_    1024
#define CL_    64            // LSTM channels per layer; gate channels = 256
#define GST    1152          // gates scratch stride (18 N-tiles of 64)
#define NT     18            // N tiles per frame
#define PLST   1160          // halves per shifted plane (16B-aligned stride)
#define KPA    72            // A smem row stride in halves
#define BST    72            // B smem row stride in halves

// ---------------- device scratch (static; no allocations) ----------------
__device__ float g_gates[(size_t)NF * 256 * GST];                 // conv outputs
// 7 shifted fp16 padded-plane copies of x and of h0 (+ front/tail guards)
__device__ __align__(16) __half g_x7[(size_t)NF * 32 * 7 * PLST + 64 + 2048];
__device__ __align__(16) __half g_h7[(size_t)NF * 64 * 7 * PLST + 64 + 2048];
// fp16 exact-split weights: [chunk][256 oc][64]  (k = [ah | al], a = ah+al exactly)
__device__ __align__(16) __half g_wp0[9  * 256 * 64];
__device__ __align__(16) __half g_wp1[18 * 256 * 64];

// taps in order {-35,-34,-33,-1,0,1,33,34,35}: shifted-copy index + extra offset
__constant__ int c_q[9]   = { 0, 1, 2, 2, 3, 4, 4, 5, 6 };
__constant__ int c_off[9] = { 0, 0, -32, 0, 0, 0, 32, 0, 0 };
__constant__ int c_tq[7]  = { -35, -34, -1, 0, 1, 34, 35 };   // shift of copy q

// ---------------- helpers ----------------
__device__ __forceinline__ float sigm(float x) { return 1.0f / (1.0f + __expf(-x)); }

__device__ __forceinline__ uint32_t smem_u32(const void* p) {
    uint32_t a;
    asm("{ .reg .u64 t; cvta.to.shared.u64 t, %1; cvt.u32.u64 %0, t; }" : "=r"(a) : "l"(p));
    return a;
}

__device__ __forceinline__ void ldsm4(uint32_t r[4], uint32_t addr) {
    asm volatile("ldmatrix.sync.aligned.m8n8.x4.shared.b16 {%0,%1,%2,%3}, [%4];"
        : "=r"(r[0]), "=r"(r[1]), "=r"(r[2]), "=r"(r[3]) : "r"(addr));
}

__device__ __forceinline__ void ldsm4t(uint32_t r[4], uint32_t addr) {
    asm volatile("ldmatrix.sync.aligned.m8n8.x4.trans.shared.b16 {%0,%1,%2,%3}, [%4];"
        : "=r"(r[0]), "=r"(r[1]), "=r"(r[2]), "=r"(r[3]) : "r"(addr));
}

__device__ __forceinline__ void mma16816(float d[4], const uint32_t a[4],
                                         uint32_t b0, uint32_t b1) {
    asm volatile(
        "mma.sync.aligned.m16n8k16.row.col.f32.f16.f16.f32 "
        "{%0,%1,%2,%3}, {%4,%5,%6,%7}, {%8,%9}, {%0,%1,%2,%3};"
        : "+f"(d[0]), "+f"(d[1]), "+f"(d[2]), "+f"(d[3])
        : "r"(a[0]), "r"(a[1]), "r"(a[2]), "r"(a[3]), "r"(b0), "r"(b1));
}

// ---------------- prologue kernels ----------------
__global__ void k_zero() {
    const uint4 z = make_uint4(0, 0, 0, 0);
    uint4* a = (uint4*)g_x7;  const size_t n1 = sizeof(g_x7) / 16;
    uint4* b = (uint4*)g_h7;  const size_t n2 = sizeof(g_h7) / 16;
    for (size_t i = blockIdx.x * blockDim.x + threadIdx.x; i < n1 + n2;
         i += (size_t)gridDim.x * blockDim.x) {
        if (i < n1) a[i] = z; else b[i - n1] = z;
    }
}

// build 7 shifted fp16 copies of padded x planes
__global__ void k_fill_x7(const float* __restrict__ x) {
    __half* xb = g_x7 + 64;
    const int n = NF * 32 * HW_;
    for (int i = blockIdx.x * blockDim.x + threadIdx.x; i < n;
         i += gridDim.x * blockDim.x) {
        int plane = i >> 10, px = i & 1023;
        int r = px >> 5, c = px & 31;
        int p = (r + 1) * 34 + (c + 1);
        __half hv = __float2half_rn(x[i]);
        __half* base = xb + (size_t)plane * 7 * PLST;
#pragma unroll
        for (int q = 0; q < 7; ++q)
            base[q * PLST + p - c_tq[q]] = hv;
    }
}

// fp16 exact split packing: chunk ch covers tap=ch/CPT, ci0=(ch%CPT)*32.
__global__ void k_pack_w(const float* __restrict__ w0, const float* __restrict__ w1) {
    const int n0 = 9 * 256 * 32, n1 = 18 * 256 * 32;
    for (int i = blockIdx.x * blockDim.x + threadIdx.x; i < n0 + n1;
         i += gridDim.x * blockDim.x) {
        if (i < n0) {
            int ci = i & 31, t = i >> 5, oc = t & 255, ch = t >> 8;  // ch = tap
            float v = w0[((size_t)oc * 32 + ci) * 9 + ch];
            __half ah = __float2half_rn(v);
            __half al = __float2half_rn(v - __half2float(ah));
            __half* p = g_wp0 + ((size_t)ch * 256 + oc) * 64;
            p[ci] = ah; p[32 + ci] = al;
        } else {
            int j = i - n0;
            int ci = j & 31, t = j >> 5, oc = t & 255, ch = t >> 8;  // ch 0..17
            int tap = ch >> 1, ci0 = (ch & 1) * 32;
            float v = w1[((size_t)oc * 64 + ci0 + ci) * 9 + tap];
            __half ah = __float2half_rn(v);
            __half al = __float2half_rn(v - __half2float(ah));
            __half* p = g_wp1 + ((size_t)ch * 256 + oc) * 64;
            p[ci] = ah; p[32 + ci] = al;
        }
    }
}

// ---------------- GEMM kernel ----------------
// CTA = 128 threads (4 warps). Tile: M=128 gate channels x N=64 padded pixels,
// one frame. Chunks of 32 ci; K_eff=64 ([ah|al] x bh, bh fragments reused).
// B comes from pre-shifted fp16 planes: fully coalesced 128-bit staging,
// [ci][px] smem layout, ldmatrix.trans.
template <int CPT>   // chunks per tap: 1 (CIN=32) or 2 (CIN=64)
__device__ __forceinline__ void gemm_body(const __half* __restrict__ bpl,
                                          const __half* __restrict__ wp,
                                          float* __restrict__ gates)
{
    __shared__ __align__(16) __half sA [128 * KPA];  // 18.4 KB
    __shared__ __align__(16) __half sBt[32 * BST];   // 4.6 KB  [ci][px]

    const int tid  = threadIdx.x, w = tid >> 5, lane = tid & 31;
    const int frame = blockIdx.x / NT, ntile = blockIdx.x - frame * NT;
    const int mtile = blockIdx.y;
    const int p0 = ntile * 64;
    const int NCH = 9 * CPT;

    const uint32_t sAu = smem_u32(sA), sBu = smem_u32(sBt);
    const size_t fbase = (size_t)frame * (CPT * 32) * 7;

    float d[2][8][4];
#pragma unroll
    for (int mt = 0; mt < 2; ++mt)
#pragma unroll
        for (int nt = 0; nt < 8; ++nt)
#pragma unroll
            for (int q = 0; q < 4; ++q) d[mt][nt][q] = 0.0f;

#pragma unroll 1
    for (int ch = 0; ch < NCH; ++ch) {
        const int tap = (CPT == 1) ? ch : (ch >> 1);
        const int ci0 = (CPT == 1) ? 0 : ((ch & 1) * 32);
        const int q   = c_q[tap];
        const int off = c_off[tap];

        __syncthreads();   // previous iter's ldsm reads done

        // ---- stage A: 128 rows x 64 halves ([ah|al]) ----
        {
            const __half* ag = wp + ((size_t)ch * 256 + mtile * 128) * 64;
            const int r8 = lane & 7, cg = lane >> 3;   // cg 0..3
#pragma unroll
            for (int ri = 0; ri < 4; ++ri) {
                int r = ri * 32 + w * 8 + r8;
#pragma unroll
                for (int cj = 0; cj < 2; ++cj) {
                    int c = cj * 4 + cg;               // 16B chunk 0..7
                    uint4 v = *(const uint4*)(ag + (size_t)r * 64 + c * 8);
                    *(uint4*)(sA + r * KPA + c * 8) = v;
                }
            }
        }
        // ---- stage B: 32 ci x 64 px fp16, coalesced from shifted planes ----
        {
            const __half* bp = bpl + (fbase + (size_t)ci0 * 7 + q) * PLST + p0 + off;
            const int ci = tid >> 3, g = tid & 7;      // 16 ci x 8 px-chunks
#pragma unroll
            for (int kk = 0; kk < 2; ++kk) {
                int cc = ci + kk * 16;
                uint4 v = *(const uint4*)(bp + (size_t)cc * (7 * PLST) + g * 8);
                *(uint4*)(sBt + cc * BST + g * 8) = v;
            }
        }
        __syncthreads();

        // ---- load B fragments once (reused across kstep pairs) ----
        uint32_t bfr[2][4][4];
#pragma unroll
        for (int kk = 0; kk < 2; ++kk)
#pragma unroll
            for (int np = 0; np < 4; ++np) {
                int ci = kk * 16 + ((lane >> 3) & 1) * 8 + (lane & 7);
                int px = np * 16 + (lane >> 4) * 8;
                ldsm4t(bfr[kk][np], sBu + (uint32_t)(ci * BST + px) * 2);
            }

        // ---- mma: 4 k-steps of 16 (ks 0,1 = ah*bh; ks 2,3 = al*bh) ----
#pragma unroll
        for (int ks = 0; ks < 4; ++ks) {
            uint32_t a[2][4];
#pragma unroll
            for (int mt = 0; mt < 2; ++mt) {
                int rowA = w * 32 + mt * 16 + (lane & 15);
                int kcol = ks * 16 + (lane >> 4) * 8;
                ldsm4(a[mt], sAu + (uint32_t)(rowA * KPA + kcol) * 2);
            }
            const int kk = ks & 1;
#pragma unroll
            for (int mt = 0; mt < 2; ++mt)
#pragma unroll
                for (int nt = 0; nt < 8; ++nt)
                    mma16816(d[mt][nt], a[mt], bfr[kk][nt >> 1][(nt & 1) * 2],
                             bfr[kk][nt >> 1][(nt & 1) * 2 + 1]);
        }
    }

    // ---- epilogue: D -> gates scratch ----
    const int g4 = lane >> 2, t4 = lane & 3;
#pragma unroll
    for (int mt = 0; mt < 2; ++mt) {
        size_t rowbase = (size_t)frame * 256 + mtile * 128 + w * 32 + mt * 16 + g4;
#pragma unroll
        for (int nt = 0; nt < 8; ++nt) {
            float* gp = gates + rowbase * GST + p0 + nt * 8 + t4 * 2;
            *(float2*)gp                     = make_float2(d[mt][nt][0], d[mt][nt][1]);
            *(float2*)(gp + 8 * (size_t)GST) = make_float2(d[mt][nt][2], d[mt][nt][3]);
        }
    }
}

__global__ void __launch_bounds__(128)
k_gemm0() { gemm_body<1>(g_x7 + 64, g_wp0, g_gates); }

__global__ void __launch_bounds__(128)
k_gemm1() { gemm_body<2>(g_h7 + 64, g_wp1, g_gates); }

// ---------------- scan kernels ----------------
// thread = (b, lstm-channel, interior pixel); loops s, cell state in register.
// PADOUT=true writes the 7 shifted fp16 plane copies for the next GEMM.
template <bool PADOUT>
__global__ void __launch_bounds__(256)
k_scan(const float* __restrict__ bias, float* __restrict__ out)
{
    int gtid = blockIdx.x * blockDim.x + threadIdx.x;  // 0 .. 262143
    int px = gtid & 1023;
    int ch = (gtid >> 10) & 63;
    int b  = gtid >> 16;
    int r = px >> 5, c = px & 31;
    int p = (r + 1) * 34 + (c + 1);

    float bi = __ldg(bias + ch);
    float bf = __ldg(bias + 64 + ch);
    float bo = __ldg(bias + 128 + ch);
    float bc = __ldg(bias + 192 + ch);

    float cst = 0.5f;
    __half* h7 = g_h7 + 64;

#pragma unroll 1
    for (int s = 0; s < S_; ++s) {
        int frame = b * S_ + s;
        const float* gg = g_gates + (size_t)frame * 256 * GST + p;
        float it = sigm(gg[(size_t)(ch)       * GST] + bi);
        float ft = sigm(gg[(size_t)(64 + ch)  * GST] + bf);
        float ot = sigm(gg[(size_t)(128 + ch) * GST] + bo);
        float cd =      gg[(size_t)(192 + ch) * GST] + bc;
        float gd = (cd >= 0.0f) ? (cd + 0.5f) : sigm(cd);
        float inv = 1.0f / (it + ft);
        cst = (ft * inv) * cst + (it * inv) * gd;
        float hv = ot * cst;
        if (PADOUT) {
            __half h16 = __float2half_rn(hv);
            __half* base = h7 + ((size_t)frame * CL_ + ch) * 7 * PLST;
#pragma unroll
            for (int q = 0; q < 7; ++q)
                base[q * PLST + p - c_tq[q]] = h16;
        } else {
            out[((size_t)frame * CL_ + ch) * HW_ + px] = hv;
        }
    }
}

// ---------------- launch ----------------
extern "C" void kernel_launch(void* const* d_in, const int* in_sizes, int n_in,
                              void* d_out, int out_size)
{
    const float* x  = (const float*)d_in[0];
    const float* w0 = (const float*)d_in[1];
    const float* b0 = (const float*)d_in[2];
    const float* w1 = (const float*)d_in[3];
    const float* b1 = (const float*)d_in[4];
    float* out = (float*)d_out;

    k_zero<<<4096, 256>>>();
    k_fill_x7<<<2048, 256>>>(x);
    k_pack_w<<<256, 256>>>(w0, w1);

    dim3 gg(NF * NT, 2, 1);   // 1152 x 2 CTAs
    k_gemm0<<<gg, 128>>>();
    k_scan<true><<<1024, 256>>>(b0, nullptr);
    k_gemm1<<<gg, 128>>>();
    k_scan<false><<<1024, 256>>>(b1, out);
}

// round 10
// speedup vs baseline: 1.6671x; 1.6671x over previous
#include <cuda_runtime.h>
#include <cuda_fp16.h>
#include <cstdint>

// ---------------- problem constants ----------------
#define B_     4
#define S_     16
#define NF     64            // frames = B*S
#define H_     32
#define W_     32
#define HW_    1024
#define CL_    64            // LSTM channels per layer; gate channels = 256
#define GST    1152          // gates scratch stride (18 N-tiles of 64)
#define NT     18            // N tiles per frame
#define PLST   1160          // halves per shifted plane (16B-aligned stride)
#define BST    72            // B smem row stride in halves

// ---------------- device scratch (static; no allocations) ----------------
__device__ float g_gates[(size_t)NF * 256 * GST];                 // conv outputs
// 7 shifted fp16 padded-plane copies of x and of h0 (+ front/tail guards)
__device__ __align__(16) __half g_x7[(size_t)NF * 32 * 7 * PLST + 64 + 2048];
__device__ __align__(16) __half g_h7[(size_t)NF * 64 * 7 * PLST + 64 + 2048];
// fragment-ordered fp16 exact-split weights:
// [chunk][mtile(2)][warp(4)][mt(2)][ks(4)][lane(32)][4 u32]  (k = [ah|al])
__device__ __align__(16) uint32_t g_wf0[9  * 8192];
__device__ __align__(16) uint32_t g_wf1[18 * 8192];

// taps in order {-35,-34,-33,-1,0,1,33,34,35}: shifted-copy index + extra offset
__constant__ int c_q[9]   = { 0, 1, 2, 2, 3, 4, 4, 5, 6 };
__constant__ int c_off[9] = { 0, 0, -32, 0, 0, 0, 32, 0, 0 };
__constant__ int c_tq[7]  = { -35, -34, -1, 0, 1, 34, 35 };   // shift of copy q

// ---------------- helpers ----------------
__device__ __forceinline__ float sigm(float x) { return 1.0f / (1.0f + __expf(-x)); }

__device__ __forceinline__ uint32_t smem_u32(const void* p) {
    uint32_t a;
    asm("{ .reg .u64 t; cvta.to.shared.u64 t, %1; cvt.u32.u64 %0, t; }" : "=r"(a) : "l"(p));
    return a;
}

__device__ __forceinline__ void ldsm4t(uint32_t r[4], uint32_t addr) {
    asm volatile("ldmatrix.sync.aligned.m8n8.x4.trans.shared.b16 {%0,%1,%2,%3}, [%4];"
        : "=r"(r[0]), "=r"(r[1]), "=r"(r[2]), "=r"(r[3]) : "r"(addr));
}

__device__ __forceinline__ void mma16816(float d[4], uint32_t a0, uint32_t a1,
                                         uint32_t a2, uint32_t a3,
                                         uint32_t b0, uint32_t b1) {
    asm volatile(
        "mma.sync.aligned.m16n8k16.row.col.f32.f16.f16.f32 "
        "{%0,%1,%2,%3}, {%4,%5,%6,%7}, {%8,%9}, {%0,%1,%2,%3};"
        : "+f"(d[0]), "+f"(d[1]), "+f"(d[2]), "+f"(d[3])
        : "r"(a0), "r"(a1), "r"(a2), "r"(a3), "r"(b0), "r"(b1));
}

// ---------------- prologue kernels ----------------
__global__ void k_zero() {
    const uint4 z = make_uint4(0, 0, 0, 0);
    uint4* a = (uint4*)g_x7;  const size_t n1 = sizeof(g_x7) / 16;
    uint4* b = (uint4*)g_h7;  const size_t n2 = sizeof(g_h7) / 16;
    for (size_t i = blockIdx.x * blockDim.x + threadIdx.x; i < n1 + n2;
         i += (size_t)gridDim.x * blockDim.x) {
        if (i < n1) a[i] = z; else b[i - n1] = z;
    }
}

// build 7 shifted fp16 copies of padded x planes
__global__ void k_fill_x7(const float* __restrict__ x) {
    __half* xb = g_x7 + 64;
    const int n = NF * 32 * HW_;
    for (int i = blockIdx.x * blockDim.x + threadIdx.x; i < n;
         i += gridDim.x * blockDim.x) {
        int plane = i >> 10, px = i & 1023;
        int r = px >> 5, c = px & 31;
        int p = (r + 1) * 34 + (c + 1);
        __half hv = __float2half_rn(x[i]);
        __half* base = xb + (size_t)plane * 7 * PLST;
#pragma unroll
        for (int q = 0; q < 7; ++q)
            base[q * PLST + p - c_tq[q]] = hv;
    }
}

// pack weights directly into mma A-fragment order.
// fragment layout (m16n8k16, row-major A): lane l, reg r:
//   row = (l>>2) + (r&1)*8 ; cols = (l&3)*2 + (r>>1)*8 + {0,1}
// k in [0,32) = ah(ci=k), k in [32,64) = al(ci=k-32); a = ah+al exactly.
__global__ void k_pack_wf(const float* __restrict__ w0, const float* __restrict__ w1) {
    const int n0 = 9 * 8192, n1 = 18 * 8192;
    for (int i = blockIdx.x * blockDim.x + threadIdx.x; i < n0 + n1;
         i += gridDim.x * blockDim.x) {
        bool l1sel = (i >= n0);
        int j = l1sel ? (i - n0) : i;
        int r     = j & 3;
        int lane  = (j >> 2) & 31;
        int ks    = (j >> 7) & 3;
        int mt    = (j >> 9) & 1;
        int w     = (j >> 10) & 3;
        int mtile = (j >> 12) & 1;
        int ch    = j >> 13;
        int row   = mtile * 128 + w * 32 + mt * 16 + (lane >> 2) + (r & 1) * 8;
        int kbase = ks * 16 + (lane & 3) * 2 + (r >> 1) * 8;
        uint32_t outv = 0;
#pragma unroll
        for (int h = 0; h < 2; ++h) {
            int k = kbase + h;
            int ci = k & 31;
            bool lo = (k >= 32);
            float v = l1sel
                ? w1[((size_t)row * 64 + (ch & 1) * 32 + ci) * 9 + (ch >> 1)]
                : w0[((size_t)row * 32 + ci) * 9 + ch];
            __half ah = __float2half_rn(v);
            __half val = lo ? __float2half_rn(v - __half2float(ah)) : ah;
            outv |= (uint32_t)__half_as_ushort(val) << (16 * h);
        }
        (l1sel ? g_wf1 : g_wf0)[j] = outv;
    }
}

// ---------------- GEMM kernel ----------------
// CTA = 128 threads (4 warps). Tile: M=128 gate channels x N=64 padded pixels,
// one frame. Chunks of 32 ci; K_eff=64 ([ah|al] x bh, bh fragments reused).
// A fragments come straight from fragment-ordered gmem (one LDG.128 each,
// L2-resident); only B goes through smem (double-buffered, ldmatrix.trans).
template <int CPT>   // chunks per tap: 1 (CIN=32) or 2 (CIN=64)
__device__ __forceinline__ void gemm_body(const __half* __restrict__ bpl,
                                          const uint32_t* __restrict__ wf,
                                          float* __restrict__ gates)
{
    __shared__ __align__(16) __half sBt[2][32 * BST];   // 9.2 KB total

    const int tid  = threadIdx.x, w = tid >> 5, lane = tid & 31;
    const int frame = blockIdx.x / NT, ntile = blockIdx.x - frame * NT;
    const int mtile = blockIdx.y;
    const int p0 = ntile * 64;
    const int NCH = 9 * CPT;

    const size_t fbase = (size_t)frame * (CPT * 32) * 7;
    const int cis = tid >> 3, gs = tid & 7;      // staging coords: 16 ci x 8 chunks

    float d[2][8][4];
#pragma unroll
    for (int mt = 0; mt < 2; ++mt)
#pragma unroll
        for (int nt = 0; nt < 8; ++nt)
#pragma unroll
            for (int q = 0; q < 4; ++q) d[mt][nt][q] = 0.0f;

#pragma unroll 1
    for (int ch = 0; ch < NCH; ++ch) {
        const int tap = (CPT == 1) ? ch : (ch >> 1);
        const int ci0 = (CPT == 1) ? 0 : ((ch & 1) * 32);
        const int q   = c_q[tap];
        const int off = c_off[tap];

        // ---- B loads (global, coalesced) ----
        const __half* bp = bpl + (fbase + (size_t)ci0 * 7 + q) * PLST + p0 + off;
        uint4 v0 = *(const uint4*)(bp + (size_t)cis * (7 * PLST) + gs * 8);
        uint4 v1 = *(const uint4*)(bp + (size_t)(cis + 16) * (7 * PLST) + gs * 8);

        // ---- A fragments: 8 independent LDG.128 ----
        const uint4* af = (const uint4*)wf + ((size_t)(ch * 2 + mtile) * 4 + w) * 256 + lane;
        uint4 afr[2][4];
#pragma unroll
        for (int mt = 0; mt < 2; ++mt)
#pragma unroll
            for (int ks = 0; ks < 4; ++ks)
                afr[mt][ks] = af[(mt * 4 + ks) * 32];

        // ---- store B into this chunk's buffer ----
        __half* sb = sBt[ch & 1];
        *(uint4*)(sb + cis * BST + gs * 8) = v0;
        *(uint4*)(sb + (cis + 16) * BST + gs * 8) = v1;
        __syncthreads();

        // ---- B fragments via ldmatrix.trans (reused across kstep pairs) ----
        const uint32_t sBu = smem_u32(sb);
        uint32_t bfr[2][4][4];
#pragma unroll
        for (int kk = 0; kk < 2; ++kk)
#pragma unroll
            for (int np = 0; np < 4; ++np) {
                int ci = kk * 16 + ((lane >> 3) & 1) * 8 + (lane & 7);
                int px = np * 16 + (lane >> 4) * 8;
                ldsm4t(bfr[kk][np], sBu + (uint32_t)(ci * BST + px) * 2);
            }

        // ---- mma: 4 k-steps of 16 (ks 0,1 = ah*bh; ks 2,3 = al*bh) ----
#pragma unroll
        for (int ks = 0; ks < 4; ++ks) {
            const int kk = ks & 1;
            const uint4 a = afr[ks >> 1][((ks & 1) << 1)];  // placeholder; fixed below
        }
        // (explicit mapping: frag index = mt-major? No — afr[mt][ks]: mt is the
        //  M subtile, ks the k-step; iterate both.)
#pragma unroll
        for (int ks = 0; ks < 4; ++ks) {
            const int kk = ks & 1;
#pragma unroll
            for (int mt = 0; mt < 2; ++mt) {
                const uint4 a = afr[mt][ks];
#pragma unroll
                for (int nt = 0; nt < 8; ++nt)
                    mma16816(d[mt][nt], a.x, a.y, a.z, a.w,
                             bfr[kk][nt >> 1][(nt & 1) * 2],
                             bfr[kk][nt >> 1][(nt & 1) * 2 + 1]);
            }
        }
    }

    // ---- epilogue: D -> gates scratch ----
    const int g4 = lane >> 2, t4 = lane & 3;
#pragma unroll
    for (int mt = 0; mt < 2; ++mt) {
        size_t rowbase = (size_t)frame * 256 + mtile * 128 + w * 32 + mt * 16 + g4;
#pragma unroll
        for (int nt = 0; nt < 8; ++nt) {
            float* gp = gates + rowbase * GST + p0 + nt * 8 + t4 * 2;
            *(float2*)gp                     = make_float2(d[mt][nt][0], d[mt][nt][1]);
            *(float2*)(gp + 8 * (size_t)GST) = make_float2(d[mt][nt][2], d[mt][nt][3]);
        }
    }
}

__global__ void __launch_bounds__(128)
k_gemm0() { gemm_body<1>(g_x7 + 64, g_wf0, g_gates); }

__global__ void __launch_bounds__(128)
k_gemm1() { gemm_body<2>(g_h7 + 64, g_wf1, g_gates); }

// ---------------- scan kernels ----------------
// thread = (b, lstm-channel, interior pixel); loops s, cell state in register.
// PADOUT=true writes the 7 shifted fp16 plane copies for the next GEMM.
template <bool PADOUT>
__global__ void __launch_bounds__(256)
k_scan(const float* __restrict__ bias, float* __restrict__ out)
{
    int gtid = blockIdx.x * blockDim.x + threadIdx.x;  // 0 .. 262143
    int px = gtid & 1023;
    int ch = (gtid >> 10) & 63;
    int b  = gtid >> 16;
    int r = px >> 5, c = px & 31;
    int p = (r + 1) * 34 + (c + 1);

    float bi = __ldg(bias + ch);
    float bf = __ldg(bias + 64 + ch);
    float bo = __ldg(bias + 128 + ch);
    float bc = __ldg(bias + 192 + ch);

    float cst = 0.5f;
    __half* h7 = g_h7 + 64;

#pragma unroll 1
    for (int s = 0; s < S_; ++s) {
        int frame = b * S_ + s;
        const float* gg = g_gates + (size_t)frame * 256 * GST + p;
        float it = sigm(gg[(size_t)(ch)       * GST] + bi);
        float ft = sigm(gg[(size_t)(64 + ch)  * GST] + bf);
        float ot = sigm(gg[(size_t)(128 + ch) * GST] + bo);
        float cd =      gg[(size_t)(192 + ch) * GST] + bc;
        float gd = (cd >= 0.0f) ? (cd + 0.5f) : sigm(cd);
        float inv = 1.0f / (it + ft);
        cst = (ft * inv) * cst + (it * inv) * gd;
        float hv = ot * cst;
        if (PADOUT) {
            __half h16 = __float2half_rn(hv);
            __half* base = h7 + ((size_t)frame * CL_ + ch) * 7 * PLST;
#pragma unroll
            for (int q = 0; q < 7; ++q)
                base[q * PLST + p - c_tq[q]] = h16;
        } else {
            out[((size_t)frame * CL_ + ch) * HW_ + px] = hv;
        }
    }
}

// ---------------- launch ----------------
extern "C" void kernel_launch(void* const* d_in, const int* in_sizes, int n_in,
                              void* d_out, int out_size)
{
    const float* x  = (const float*)d_in[0];
    const float* w0 = (const float*)d_in[1];
    const float* b0 = (const float*)d_in[2];
    const float* w1 = (const float*)d_in[3];
    const float* b1 = (const float*)d_in[4];
    float* out = (float*)d_out;

    k_zero<<<4096, 256>>>();
    k_fill_x7<<<2048, 256>>>(x);
    k_pack_wf<<<512, 256>>>(w0, w1);

    dim3 gg(NF * NT, 2, 1);   // 1152 x 2 CTAs
    k_gemm0<<<gg, 128>>>();
    k_scan<true><<<1024, 256>>>(b0, nullptr);
    k_gemm1<<<gg, 128>>>();
    k_scan<false><<<1024, 256>>>(b1, out);
}